// round 10
// baseline (speedup 1.0000x reference)
#include <cuda_runtime.h>
#include <cuda_bf16.h>
#include <math.h>
#include <stdint.h>

#define DIMD   512
#define HEADS  8
#define HD     64
#define MLPD   2048
#define BATCH  2
#define SEQ    4096
#define BN_TOK 8192   // BATCH*SEQ

// ---------------- scratch (static device arrays; no allocation) -------------
__device__ float g_h  [(size_t)BN_TOK * DIMD];
__device__ float g_q  [(size_t)BN_TOK * DIMD];
__device__ float g_k  [(size_t)BN_TOK * DIMD];
__device__ float g_v  [(size_t)BN_TOK * DIMD];
__device__ float g_att[(size_t)BN_TOK * DIMD];
__device__ float g_xm [(size_t)BN_TOK * DIMD];
__device__ float g_ff [(size_t)BN_TOK * MLPD];

__device__ __forceinline__ float gelu_exact(float x) {
    return 0.5f * x * (1.0f + erff(x * 0.70710678118654752440f));
}

// tf32 helpers ---------------------------------------------------------------
__device__ __forceinline__ void mma_tf32(float* c, const uint32_t* a, const uint32_t* b) {
    asm volatile(
        "mma.sync.aligned.m16n8k8.row.col.f32.tf32.tf32.f32 "
        "{%0,%1,%2,%3},{%4,%5,%6,%7},{%8,%9},{%0,%1,%2,%3};\n"
        : "+f"(c[0]), "+f"(c[1]), "+f"(c[2]), "+f"(c[3])
        : "r"(a[0]), "r"(a[1]), "r"(a[2]), "r"(a[3]), "r"(b[0]), "r"(b[1]));
}

// bf16 helpers ---------------------------------------------------------------
__device__ __forceinline__ void mma_bf16(float* c, const uint32_t* a, const uint32_t* b) {
    asm volatile(
        "mma.sync.aligned.m16n8k16.row.col.f32.bf16.bf16.f32 "
        "{%0,%1,%2,%3},{%4,%5,%6,%7},{%8,%9},{%0,%1,%2,%3};\n"
        : "+f"(c[0]), "+f"(c[1]), "+f"(c[2]), "+f"(c[3])
        : "r"(a[0]), "r"(a[1]), "r"(a[2]), "r"(a[3]), "r"(b[0]), "r"(b[1]));
}

__device__ __forceinline__ uint32_t pack2_bf16(float a, float b) {
    __nv_bfloat162 t = __floats2bfloat162_rn(a, b);
    return *reinterpret_cast<uint32_t*>(&t);
}

__device__ __forceinline__ void split_bf16(float x, float& hi, float& lo) {
    hi = __bfloat162float(__float2bfloat16_rn(x));
    lo = x - hi;
}

// ---------------- LayerNorm: one block (128 thr) per row of 512 -------------
__global__ void ln_kernel(const float* __restrict__ x, const float* __restrict__ g,
                          const float* __restrict__ be, float* __restrict__ out) {
    int row = blockIdx.x;
    int t = threadIdx.x;
    const float4* xr = (const float4*)(x + (size_t)row * DIMD);
    float4 v = xr[t];
    float s  = v.x + v.y + v.z + v.w;
    float sq = v.x * v.x + v.y * v.y + v.z * v.z + v.w * v.w;
    #pragma unroll
    for (int o = 16; o > 0; o >>= 1) {
        s  += __shfl_xor_sync(0xffffffffu, s,  o);
        sq += __shfl_xor_sync(0xffffffffu, sq, o);
    }
    __shared__ float rs_[4], rq_[4];
    int lane = t & 31, w = t >> 5;
    if (lane == 0) { rs_[w] = s; rq_[w] = sq; }
    __syncthreads();
    s  = rs_[0] + rs_[1] + rs_[2] + rs_[3];
    sq = rq_[0] + rq_[1] + rq_[2] + rq_[3];
    float mu  = s * (1.0f / DIMD);
    float var = sq * (1.0f / DIMD) - mu * mu;
    float rstd = rsqrtf(var + 1e-5f);
    float4 gg = ((const float4*)g)[t];
    float4 bb = ((const float4*)be)[t];
    float4 o4;
    o4.x = (v.x - mu) * rstd * gg.x + bb.x;
    o4.y = (v.y - mu) * rstd * gg.y + bb.y;
    o4.z = (v.z - mu) * rstd * gg.z + bb.z;
    o4.w = (v.w - mu) * rstd * gg.w + bb.w;
    ((float4*)(out + (size_t)row * DIMD))[t] = o4;
}

// ---------------- tf32 tensor-core NN GEMM (2-stage pipelined) --------------
// C[M,N] = A[M,K] @ B[K,N] (+epilogue). BM=128, BN=128, BK=16, 256 threads.
// Register-staged double buffer: prefetch next tile during compute; one sync
// per k-iteration.
// EPI: 0=none, 1=+bias, 2=+bias,gelu, 3=+bias,+residual
template <int EPI>
__global__ __launch_bounds__(256, 2) void gemm_tf32(
    const float* __restrict__ A, const float* __restrict__ Bm,
    const float* __restrict__ bias, const float* __restrict__ R,
    float* __restrict__ C, int M, int Ncols, int K)
{
    __shared__ float As[2][128][20];
    __shared__ float Bs[2][16][136];

    int tid = threadIdx.x, wid = tid >> 5, lane = tid & 31;
    int gid = lane >> 2, tg = lane & 3;
    int warpM = wid & 1, warpN = wid >> 1;
    int rowTile = blockIdx.y * 128, colTile = blockIdx.x * 128;

    // per-thread load coords
    int ar0 = tid >> 2,          ac = (tid & 3) * 4;          // A: rows ar0, ar0+64
    int br0 = tid >> 5,          bc = (tid & 31) * 4;         // B: rows br0, br0+8

    const float* Ap0 = A  + (size_t)(rowTile + ar0)      * K + ac;
    const float* Ap1 = A  + (size_t)(rowTile + ar0 + 64) * K + ac;
    const float* Bp0 = Bm + (size_t)br0       * Ncols + colTile + bc;
    const float* Bp1 = Bm + (size_t)(br0 + 8) * Ncols + colTile + bc;

    float acc[4][4][4] = {};

    // prologue: load tile 0, store to stage 0
    float4 na0 = *(const float4*)Ap0;
    float4 na1 = *(const float4*)Ap1;
    float4 nb0 = *(const float4*)Bp0;
    float4 nb1 = *(const float4*)Bp1;
    *(float4*)&As[0][ar0     ][ac] = na0;
    *(float4*)&As[0][ar0 + 64][ac] = na1;
    *(float4*)&Bs[0][br0     ][bc] = nb0;
    *(float4*)&Bs[0][br0 + 8 ][bc] = nb1;
    __syncthreads();

    int nIter = K >> 4;
    int cur = 0;
    for (int it = 0; it < nIter; it++) {
        bool hasNext = (it + 1) < nIter;
        if (hasNext) {
            int koff = (it + 1) * 16;
            na0 = *(const float4*)(Ap0 + koff);
            na1 = *(const float4*)(Ap1 + koff);
            nb0 = *(const float4*)(Bp0 + (size_t)koff * Ncols);
            nb1 = *(const float4*)(Bp1 + (size_t)koff * Ncols);
        }

        #pragma unroll
        for (int ks = 0; ks < 16; ks += 8) {
            uint32_t af[4][4], bf[4][2];
            #pragma unroll
            for (int mt = 0; mt < 4; mt++) {
                int rb = warpM * 64 + mt * 16;
                af[mt][0] = __float_as_uint(As[cur][rb + gid    ][ks + tg    ]);
                af[mt][1] = __float_as_uint(As[cur][rb + gid + 8][ks + tg    ]);
                af[mt][2] = __float_as_uint(As[cur][rb + gid    ][ks + tg + 4]);
                af[mt][3] = __float_as_uint(As[cur][rb + gid + 8][ks + tg + 4]);
            }
            #pragma unroll
            for (int nt = 0; nt < 4; nt++) {
                int nb = warpN * 32 + nt * 8;
                bf[nt][0] = __float_as_uint(Bs[cur][ks + tg    ][nb + gid]);
                bf[nt][1] = __float_as_uint(Bs[cur][ks + tg + 4][nb + gid]);
            }
            #pragma unroll
            for (int mt = 0; mt < 4; mt++)
                #pragma unroll
                for (int nt = 0; nt < 4; nt++)
                    mma_tf32(acc[mt][nt], af[mt], bf[nt]);
        }

        if (hasNext) {
            int nxt = cur ^ 1;
            *(float4*)&As[nxt][ar0     ][ac] = na0;
            *(float4*)&As[nxt][ar0 + 64][ac] = na1;
            *(float4*)&Bs[nxt][br0     ][bc] = nb0;
            *(float4*)&Bs[nxt][br0 + 8 ][bc] = nb1;
        }
        __syncthreads();
        cur ^= 1;
    }

    #pragma unroll
    for (int mt = 0; mt < 4; mt++) {
        #pragma unroll
        for (int nt = 0; nt < 4; nt++) {
            int col  = colTile + warpN * 32 + nt * 8 + tg * 2;
            int row0 = rowTile + warpM * 64 + mt * 16 + gid;
            int row1 = row0 + 8;
            float2 o0 = make_float2(acc[mt][nt][0], acc[mt][nt][1]);
            float2 o1 = make_float2(acc[mt][nt][2], acc[mt][nt][3]);
            if (EPI >= 1) {
                float b0 = bias[col], b1 = bias[col + 1];
                o0.x += b0; o0.y += b1; o1.x += b0; o1.y += b1;
            }
            if (EPI == 2) {
                o0.x = gelu_exact(o0.x); o0.y = gelu_exact(o0.y);
                o1.x = gelu_exact(o1.x); o1.y = gelu_exact(o1.y);
            }
            if (EPI == 3) {
                const float* r0p = R + (size_t)row0 * Ncols + col;
                const float* r1p = R + (size_t)row1 * Ncols + col;
                o0.x += r0p[0]; o0.y += r0p[1];
                o1.x += r1p[0]; o1.y += r1p[1];
            }
            *(float2*)(C + (size_t)row0 * Ncols + col) = o0;
            *(float2*)(C + (size_t)row1 * Ncols + col) = o1;
        }
    }
}

// ---------------- bf16x3 GEMM (fp32-accurate, 2-stage pipelined) ------------
// C = A @ B via bf16 hi/lo split: hi*hi + hi*lo + lo*hi (m16n8k16 HMMA).
// Same register-staged double buffer; split happens at smem-store time.
template <int EPI>
__global__ __launch_bounds__(256, 2) void gemm_bf16x3(
    const float* __restrict__ A, const float* __restrict__ Bm,
    const float* __restrict__ bias, const float* __restrict__ R,
    float* __restrict__ C, int M, int Ncols, int K)
{
    __shared__ uint32_t Ah[2][128][12], Al[2][128][12];
    __shared__ uint32_t Bh[2][128][12], Bl[2][128][12];

    int tid = threadIdx.x, wid = tid >> 5, lane = tid & 31;
    int gid = lane >> 2, tg = lane & 3;
    int warpM = wid & 1, warpN = wid >> 1;
    int rowTile = blockIdx.y * 128, colTile = blockIdx.x * 128;

    // A: each thread 2 float4 at rows ar0, ar0+64, k-offset ac
    int ar0 = tid >> 2, ac = (tid & 3) * 4;
    // B: thread = (kpair k2, 4 cols n4)
    int k2 = tid & 7, n4 = (tid >> 3) * 4;

    const float* Ap0 = A + (size_t)(rowTile + ar0)      * K + ac;
    const float* Ap1 = A + (size_t)(rowTile + ar0 + 64) * K + ac;
    const float* Bp  = Bm + (size_t)(2 * k2) * Ncols + colTile + n4;

    float acc[4][4][4] = {};

    float4 na0, na1, nb0, nb1;

    // store helper (split + pack into stage st)
    auto store_tiles = [&](int st, float4 a0, float4 a1, float4 b0, float4 b1) {
        int p = ac >> 1;
        float hx, lx, hy, ly, hz, lz, hw, lw;
        split_bf16(a0.x, hx, lx); split_bf16(a0.y, hy, ly);
        split_bf16(a0.z, hz, lz); split_bf16(a0.w, hw, lw);
        Ah[st][ar0][p]     = pack2_bf16(hx, hy);
        Ah[st][ar0][p + 1] = pack2_bf16(hz, hw);
        Al[st][ar0][p]     = pack2_bf16(lx, ly);
        Al[st][ar0][p + 1] = pack2_bf16(lz, lw);
        split_bf16(a1.x, hx, lx); split_bf16(a1.y, hy, ly);
        split_bf16(a1.z, hz, lz); split_bf16(a1.w, hw, lw);
        Ah[st][ar0 + 64][p]     = pack2_bf16(hx, hy);
        Ah[st][ar0 + 64][p + 1] = pack2_bf16(hz, hw);
        Al[st][ar0 + 64][p]     = pack2_bf16(lx, ly);
        Al[st][ar0 + 64][p + 1] = pack2_bf16(lz, lw);
        float h0, l0, h1, l1;
        split_bf16(b0.x, h0, l0); split_bf16(b1.x, h1, l1);
        Bh[st][n4 + 0][k2] = pack2_bf16(h0, h1);  Bl[st][n4 + 0][k2] = pack2_bf16(l0, l1);
        split_bf16(b0.y, h0, l0); split_bf16(b1.y, h1, l1);
        Bh[st][n4 + 1][k2] = pack2_bf16(h0, h1);  Bl[st][n4 + 1][k2] = pack2_bf16(l0, l1);
        split_bf16(b0.z, h0, l0); split_bf16(b1.z, h1, l1);
        Bh[st][n4 + 2][k2] = pack2_bf16(h0, h1);  Bl[st][n4 + 2][k2] = pack2_bf16(l0, l1);
        split_bf16(b0.w, h0, l0); split_bf16(b1.w, h1, l1);
        Bh[st][n4 + 3][k2] = pack2_bf16(h0, h1);  Bl[st][n4 + 3][k2] = pack2_bf16(l0, l1);
    };

    // prologue
    na0 = *(const float4*)Ap0;
    na1 = *(const float4*)Ap1;
    nb0 = *(const float4*)Bp;
    nb1 = *(const float4*)(Bp + Ncols);
    store_tiles(0, na0, na1, nb0, nb1);
    __syncthreads();

    int nIter = K >> 4;
    int cur = 0;
    for (int it = 0; it < nIter; it++) {
        bool hasNext = (it + 1) < nIter;
        if (hasNext) {
            int koff = (it + 1) * 16;
            na0 = *(const float4*)(Ap0 + koff);
            na1 = *(const float4*)(Ap1 + koff);
            nb0 = *(const float4*)(Bp + (size_t)koff * Ncols);
            nb1 = *(const float4*)(Bp + (size_t)(koff + 1) * Ncols);
        }

        uint32_t ah[4][4], al[4][4], bh[4][2], bl[4][2];
        #pragma unroll
        for (int mt = 0; mt < 4; mt++) {
            int rb = warpM * 64 + mt * 16;
            ah[mt][0] = Ah[cur][rb + gid    ][tg    ];
            ah[mt][1] = Ah[cur][rb + gid + 8][tg    ];
            ah[mt][2] = Ah[cur][rb + gid    ][tg + 4];
            ah[mt][3] = Ah[cur][rb + gid + 8][tg + 4];
            al[mt][0] = Al[cur][rb + gid    ][tg    ];
            al[mt][1] = Al[cur][rb + gid + 8][tg    ];
            al[mt][2] = Al[cur][rb + gid    ][tg + 4];
            al[mt][3] = Al[cur][rb + gid + 8][tg + 4];
        }
        #pragma unroll
        for (int nt = 0; nt < 4; nt++) {
            int nb = warpN * 32 + nt * 8;
            bh[nt][0] = Bh[cur][nb + gid][tg    ];
            bh[nt][1] = Bh[cur][nb + gid][tg + 4];
            bl[nt][0] = Bl[cur][nb + gid][tg    ];
            bl[nt][1] = Bl[cur][nb + gid][tg + 4];
        }
        #pragma unroll
        for (int mt = 0; mt < 4; mt++)
            #pragma unroll
            for (int nt = 0; nt < 4; nt++) {
                mma_bf16(acc[mt][nt], ah[mt], bh[nt]);
                mma_bf16(acc[mt][nt], ah[mt], bl[nt]);
                mma_bf16(acc[mt][nt], al[mt], bh[nt]);
            }

        if (hasNext) store_tiles(cur ^ 1, na0, na1, nb0, nb1);
        __syncthreads();
        cur ^= 1;
    }

    #pragma unroll
    for (int mt = 0; mt < 4; mt++) {
        #pragma unroll
        for (int nt = 0; nt < 4; nt++) {
            int col  = colTile + warpN * 32 + nt * 8 + tg * 2;
            int row0 = rowTile + warpM * 64 + mt * 16 + gid;
            int row1 = row0 + 8;
            float2 o0 = make_float2(acc[mt][nt][0], acc[mt][nt][1]);
            float2 o1 = make_float2(acc[mt][nt][2], acc[mt][nt][3]);
            if (EPI >= 1) {
                float b0 = bias[col], b1 = bias[col + 1];
                o0.x += b0; o0.y += b1; o1.x += b0; o1.y += b1;
            }
            if (EPI == 2) {
                o0.x = gelu_exact(o0.x); o0.y = gelu_exact(o0.y);
                o1.x = gelu_exact(o1.x); o1.y = gelu_exact(o1.y);
            }
            if (EPI == 3) {
                const float* r0p = R + (size_t)row0 * Ncols + col;
                const float* r1p = R + (size_t)row1 * Ncols + col;
                o0.x += r0p[0]; o0.y += r0p[1];
                o1.x += r1p[0]; o1.y += r1p[1];
            }
            *(float2*)(C + (size_t)row0 * Ncols + col) = o0;
            *(float2*)(C + (size_t)row1 * Ncols + col) = o1;
        }
    }
}

// ---------------- Flash attention (tf32 MMA, online softmax) ----------------
#define FLDS 68
#define FSM_BYTES (3 * 64 * FLDS * 4)

__global__ __launch_bounds__(128, 3) void flash_tf32(
    const float* __restrict__ qp, const float* __restrict__ kp,
    const float* __restrict__ vp, float* __restrict__ att)
{
    extern __shared__ float sm_[];
    float* Ks = sm_;
    float* Vs = sm_ + 64 * FLDS;
    float* Ps = sm_ + 2 * 64 * FLDS;   // also Q staging

    int z = blockIdx.y, b = z >> 3, hh = z & 7;
    const float* Q = qp + (size_t)b * SEQ * DIMD + hh * HD;
    const float* K = kp + (size_t)b * SEQ * DIMD + hh * HD;
    const float* V = vp + (size_t)b * SEQ * DIMD + hh * HD;
    float* O = att + (size_t)b * SEQ * DIMD + hh * HD;
    int q0 = blockIdx.x * 64;

    int tid = threadIdx.x, wid = tid >> 5, lane = tid & 31;
    int gid = lane >> 2, tg = lane & 3;
    int rb = wid * 16;

    for (int idx = tid; idx < 64 * 16; idx += 128) {
        int r = idx >> 4, c4 = (idx & 15) * 4;
        float4 a = *(const float4*)(Q + (size_t)(q0 + r) * DIMD + c4);
        a.x *= 0.125f; a.y *= 0.125f; a.z *= 0.125f; a.w *= 0.125f;
        *(float4*)&Ps[r * FLDS + c4] = a;
    }
    __syncthreads();
    uint32_t qf[8][4];
    #pragma unroll
    for (int ki = 0; ki < 8; ki++) {
        int ks = ki * 8;
        qf[ki][0] = __float_as_uint(Ps[(rb + gid    ) * FLDS + ks + tg    ]);
        qf[ki][1] = __float_as_uint(Ps[(rb + gid + 8) * FLDS + ks + tg    ]);
        qf[ki][2] = __float_as_uint(Ps[(rb + gid    ) * FLDS + ks + tg + 4]);
        qf[ki][3] = __float_as_uint(Ps[(rb + gid + 8) * FLDS + ks + tg + 4]);
    }
    __syncthreads();

    float m0 = -1e30f, m1 = -1e30f, l0 = 0.0f, l1 = 0.0f;
    float o[8][4] = {};

    for (int t0 = 0; t0 < SEQ; t0 += 64) {
        for (int idx = tid; idx < 64 * 16; idx += 128) {
            int r = idx >> 4, c4 = (idx & 15) * 4;
            *(float4*)&Ks[r * FLDS + c4] =
                *(const float4*)(K + (size_t)(t0 + r) * DIMD + c4);
            *(float4*)&Vs[r * FLDS + c4] =
                *(const float4*)(V + (size_t)(t0 + r) * DIMD + c4);
        }
        __syncthreads();

        float s[8][4] = {};
        #pragma unroll
        for (int ki = 0; ki < 8; ki++) {
            int ks = ki * 8;
            #pragma unroll
            for (int nt = 0; nt < 8; nt++) {
                uint32_t bf[2];
                bf[0] = __float_as_uint(Ks[(nt * 8 + gid) * FLDS + ks + tg    ]);
                bf[1] = __float_as_uint(Ks[(nt * 8 + gid) * FLDS + ks + tg + 4]);
                mma_tf32(s[nt], qf[ki], bf);
            }
        }

        float tm0 = -1e30f, tm1 = -1e30f;
        #pragma unroll
        for (int nt = 0; nt < 8; nt++) {
            tm0 = fmaxf(tm0, fmaxf(s[nt][0], s[nt][1]));
            tm1 = fmaxf(tm1, fmaxf(s[nt][2], s[nt][3]));
        }
        tm0 = fmaxf(tm0, __shfl_xor_sync(0xffffffffu, tm0, 1));
        tm0 = fmaxf(tm0, __shfl_xor_sync(0xffffffffu, tm0, 2));
        tm1 = fmaxf(tm1, __shfl_xor_sync(0xffffffffu, tm1, 1));
        tm1 = fmaxf(tm1, __shfl_xor_sync(0xffffffffu, tm1, 2));
        float nm0 = fmaxf(m0, tm0), nm1 = fmaxf(m1, tm1);
        float r0 = __expf(m0 - nm0), r1 = __expf(m1 - nm1);
        float sum0 = 0.0f, sum1 = 0.0f;
        #pragma unroll
        for (int nt = 0; nt < 8; nt++) {
            s[nt][0] = __expf(s[nt][0] - nm0);
            s[nt][1] = __expf(s[nt][1] - nm0);
            s[nt][2] = __expf(s[nt][2] - nm1);
            s[nt][3] = __expf(s[nt][3] - nm1);
            sum0 += s[nt][0] + s[nt][1];
            sum1 += s[nt][2] + s[nt][3];
        }
        sum0 += __shfl_xor_sync(0xffffffffu, sum0, 1);
        sum0 += __shfl_xor_sync(0xffffffffu, sum0, 2);
        sum1 += __shfl_xor_sync(0xffffffffu, sum1, 1);
        sum1 += __shfl_xor_sync(0xffffffffu, sum1, 2);
        l0 = l0 * r0 + sum0;
        l1 = l1 * r1 + sum1;
        m0 = nm0; m1 = nm1;
        #pragma unroll
        for (int nt = 0; nt < 8; nt++) {
            o[nt][0] *= r0; o[nt][1] *= r0;
            o[nt][2] *= r1; o[nt][3] *= r1;
        }

        #pragma unroll
        for (int nt = 0; nt < 8; nt++) {
            *(float2*)&Ps[(rb + gid    ) * FLDS + nt * 8 + tg * 2] =
                make_float2(s[nt][0], s[nt][1]);
            *(float2*)&Ps[(rb + gid + 8) * FLDS + nt * 8 + tg * 2] =
                make_float2(s[nt][2], s[nt][3]);
        }
        __syncthreads();

        #pragma unroll
        for (int ki = 0; ki < 8; ki++) {
            int ks = ki * 8;
            uint32_t af[4];
            af[0] = __float_as_uint(Ps[(rb + gid    ) * FLDS + ks + tg    ]);
            af[1] = __float_as_uint(Ps[(rb + gid + 8) * FLDS + ks + tg    ]);
            af[2] = __float_as_uint(Ps[(rb + gid    ) * FLDS + ks + tg + 4]);
            af[3] = __float_as_uint(Ps[(rb + gid + 8) * FLDS + ks + tg + 4]);
            #pragma unroll
            for (int nt = 0; nt < 8; nt++) {
                uint32_t bf[2];
                bf[0] = __float_as_uint(Vs[(ks + tg    ) * FLDS + nt * 8 + gid]);
                bf[1] = __float_as_uint(Vs[(ks + tg + 4) * FLDS + nt * 8 + gid]);
                mma_tf32(o[nt], af, bf);
            }
        }
        __syncthreads();
    }

    float inv0 = 1.0f / l0, inv1 = 1.0f / l1;
    int row0 = q0 + rb + gid, row1 = row0 + 8;
    #pragma unroll
    for (int nt = 0; nt < 8; nt++) {
        int col = nt * 8 + tg * 2;
        *(float2*)(O + (size_t)row0 * DIMD + col) =
            make_float2(o[nt][0] * inv0, o[nt][1] * inv0);
        *(float2*)(O + (size_t)row1 * DIMD + col) =
            make_float2(o[nt][2] * inv1, o[nt][3] * inv1);
    }
}

// ---------------- launch ----------------------------------------------------
extern "C" void kernel_launch(void* const* d_in, const int* in_sizes, int n_in,
                              void* d_out, int out_size) {
    const float* x   = (const float*)d_in[0];
    const float* Wq  = (const float*)d_in[1];
    const float* Wk  = (const float*)d_in[2];
    const float* Wv  = (const float*)d_in[3];
    const float* Wo  = (const float*)d_in[4];
    const float* bo  = (const float*)d_in[5];
    const float* W1  = (const float*)d_in[6];
    const float* b1  = (const float*)d_in[7];
    const float* W2  = (const float*)d_in[8];
    const float* b2  = (const float*)d_in[9];
    const float* g1  = (const float*)d_in[10];
    const float* be1 = (const float*)d_in[11];
    const float* g2  = (const float*)d_in[12];
    const float* be2 = (const float*)d_in[13];
    float* out = (float*)d_out;

    float *h, *q, *k, *v, *att, *xm, *ff;
    cudaGetSymbolAddress((void**)&h,   g_h);
    cudaGetSymbolAddress((void**)&q,   g_q);
    cudaGetSymbolAddress((void**)&k,   g_k);
    cudaGetSymbolAddress((void**)&v,   g_v);
    cudaGetSymbolAddress((void**)&att, g_att);
    cudaGetSymbolAddress((void**)&xm,  g_xm);
    cudaGetSymbolAddress((void**)&ff,  g_ff);

    cudaFuncSetAttribute(flash_tf32,
                         cudaFuncAttributeMaxDynamicSharedMemorySize, FSM_BYTES);

    dim3 gProj(DIMD / 128, BN_TOK / 128);       // (4, 64)
    dim3 gMlp(MLPD / 128, BN_TOK / 128);        // (16, 64)

    // 1) h = LN(x; g1, be1)
    ln_kernel<<<BN_TOK, 128>>>(x, g1, be1, h);
    // 2) q, k, v projections (single-pass tf32)
    gemm_tf32<0><<<gProj, 256>>>(h, Wq, nullptr, nullptr, q, BN_TOK, DIMD, DIMD);
    gemm_tf32<0><<<gProj, 256>>>(h, Wk, nullptr, nullptr, k, BN_TOK, DIMD, DIMD);
    gemm_tf32<0><<<gProj, 256>>>(h, Wv, nullptr, nullptr, v, BN_TOK, DIMD, DIMD);
    // 3-5) fused flash attention
    flash_tf32<<<dim3(SEQ / 64, BATCH * HEADS), 128, FSM_BYTES>>>(q, k, v, att);
    // 6) xm = x + att @ Wo + bo
    gemm_tf32<3><<<gProj, 256>>>(att, Wo, bo, x, xm, BN_TOK, DIMD, DIMD);
    // 7) h = LN(xm; g2, be2)
    ln_kernel<<<BN_TOK, 128>>>(xm, g2, be2, h);
    // 8) ff = gelu(h @ W1 + b1)   (bf16x3 split)
    gemm_bf16x3<2><<<gMlp, 256>>>(h, W1, b1, nullptr, ff, BN_TOK, MLPD, DIMD);
    // 9) out = xm + ff @ W2 + b2  (bf16x3 split)
    gemm_bf16x3<3><<<gProj, 256>>>(ff, W2, b2, xm, out, BN_TOK, DIMD, MLPD);
}

// round 11
// speedup vs baseline: 1.0196x; 1.0196x over previous
#include <cuda_runtime.h>
#include <cuda_bf16.h>
#include <math.h>
#include <stdint.h>

#define DIMD   512
#define HEADS  8
#define HD     64
#define MLPD   2048
#define BATCH  2
#define SEQ    4096
#define BN_TOK 8192   // BATCH*SEQ

// ---------------- scratch (static device arrays; no allocation) -------------
__device__ float g_h  [(size_t)BN_TOK * DIMD];
__device__ float g_q  [(size_t)BN_TOK * DIMD];
__device__ float g_k  [(size_t)BN_TOK * DIMD];
__device__ float g_v  [(size_t)BN_TOK * DIMD];
__device__ float g_att[(size_t)BN_TOK * DIMD];
__device__ float g_xm [(size_t)BN_TOK * DIMD];
__device__ __nv_bfloat16 g_h2h[(size_t)BN_TOK * DIMD];
__device__ __nv_bfloat16 g_h2l[(size_t)BN_TOK * DIMD];
__device__ __nv_bfloat16 g_ffh[(size_t)BN_TOK * MLPD];
__device__ __nv_bfloat16 g_ffl[(size_t)BN_TOK * MLPD];
__device__ __nv_bfloat16 g_w1h[(size_t)MLPD * DIMD];   // W1^T hi  [2048][512]
__device__ __nv_bfloat16 g_w1l[(size_t)MLPD * DIMD];
__device__ __nv_bfloat16 g_w2h[(size_t)DIMD * MLPD];   // W2^T hi  [512][2048]
__device__ __nv_bfloat16 g_w2l[(size_t)DIMD * MLPD];

__device__ __forceinline__ float gelu_exact(float x) {
    return 0.5f * x * (1.0f + erff(x * 0.70710678118654752440f));
}

// tf32 helpers ---------------------------------------------------------------
__device__ __forceinline__ void mma_tf32(float* c, const uint32_t* a, const uint32_t* b) {
    asm volatile(
        "mma.sync.aligned.m16n8k8.row.col.f32.tf32.tf32.f32 "
        "{%0,%1,%2,%3},{%4,%5,%6,%7},{%8,%9},{%0,%1,%2,%3};\n"
        : "+f"(c[0]), "+f"(c[1]), "+f"(c[2]), "+f"(c[3])
        : "r"(a[0]), "r"(a[1]), "r"(a[2]), "r"(a[3]), "r"(b[0]), "r"(b[1]));
}

// bf16 helpers ---------------------------------------------------------------
__device__ __forceinline__ void mma_bf16(float* c, const uint32_t* a, const uint32_t* b) {
    asm volatile(
        "mma.sync.aligned.m16n8k16.row.col.f32.bf16.bf16.f32 "
        "{%0,%1,%2,%3},{%4,%5,%6,%7},{%8,%9},{%0,%1,%2,%3};\n"
        : "+f"(c[0]), "+f"(c[1]), "+f"(c[2]), "+f"(c[3])
        : "r"(a[0]), "r"(a[1]), "r"(a[2]), "r"(a[3]), "r"(b[0]), "r"(b[1]));
}

__device__ __forceinline__ void split_bf16(float x, __nv_bfloat16& hi, __nv_bfloat16& lo) {
    hi = __float2bfloat16_rn(x);
    lo = __float2bfloat16_rn(x - __bfloat162float(hi));
}

// ---------------- weight transpose + split: W[K][N] -> T_hi/lo[N][K] --------
__global__ void wsplit_kernel(const float* __restrict__ W,
                              __nv_bfloat16* __restrict__ Th,
                              __nv_bfloat16* __restrict__ Tl,
                              int K, int N) {
    __shared__ float tile[32][33];
    int kb = blockIdx.y * 32, nb = blockIdx.x * 32;
    int tx = threadIdx.x, ty = threadIdx.y;   // 32 x 8
    #pragma unroll
    for (int i = 0; i < 32; i += 8)
        tile[ty + i][tx] = W[(size_t)(kb + ty + i) * N + nb + tx];
    __syncthreads();
    #pragma unroll
    for (int i = 0; i < 32; i += 8) {
        float v = tile[tx][ty + i];           // W[kb+tx][nb+ty+i]
        __nv_bfloat16 hi, lo;
        split_bf16(v, hi, lo);
        size_t o = (size_t)(nb + ty + i) * K + kb + tx;
        Th[o] = hi;
        Tl[o] = lo;
    }
}

// ---------------- LayerNorm (fp32 out) --------------------------------------
__global__ void ln_kernel(const float* __restrict__ x, const float* __restrict__ g,
                          const float* __restrict__ be, float* __restrict__ out) {
    int row = blockIdx.x;
    int t = threadIdx.x;
    const float4* xr = (const float4*)(x + (size_t)row * DIMD);
    float4 v = xr[t];
    float s  = v.x + v.y + v.z + v.w;
    float sq = v.x * v.x + v.y * v.y + v.z * v.z + v.w * v.w;
    #pragma unroll
    for (int o = 16; o > 0; o >>= 1) {
        s  += __shfl_xor_sync(0xffffffffu, s,  o);
        sq += __shfl_xor_sync(0xffffffffu, sq, o);
    }
    __shared__ float rs_[4], rq_[4];
    int lane = t & 31, w = t >> 5;
    if (lane == 0) { rs_[w] = s; rq_[w] = sq; }
    __syncthreads();
    s  = rs_[0] + rs_[1] + rs_[2] + rs_[3];
    sq = rq_[0] + rq_[1] + rq_[2] + rq_[3];
    float mu  = s * (1.0f / DIMD);
    float var = sq * (1.0f / DIMD) - mu * mu;
    float rstd = rsqrtf(var + 1e-5f);
    float4 gg = ((const float4*)g)[t];
    float4 bb = ((const float4*)be)[t];
    float4 o4;
    o4.x = (v.x - mu) * rstd * gg.x + bb.x;
    o4.y = (v.y - mu) * rstd * gg.y + bb.y;
    o4.z = (v.z - mu) * rstd * gg.z + bb.z;
    o4.w = (v.w - mu) * rstd * gg.w + bb.w;
    ((float4*)(out + (size_t)row * DIMD))[t] = o4;
}

// ---------------- LayerNorm (bf16 hi/lo out) --------------------------------
__global__ void ln_bf16_kernel(const float* __restrict__ x, const float* __restrict__ g,
                               const float* __restrict__ be,
                               __nv_bfloat16* __restrict__ oh,
                               __nv_bfloat16* __restrict__ ol) {
    int row = blockIdx.x;
    int t = threadIdx.x;
    const float4* xr = (const float4*)(x + (size_t)row * DIMD);
    float4 v = xr[t];
    float s  = v.x + v.y + v.z + v.w;
    float sq = v.x * v.x + v.y * v.y + v.z * v.z + v.w * v.w;
    #pragma unroll
    for (int o = 16; o > 0; o >>= 1) {
        s  += __shfl_xor_sync(0xffffffffu, s,  o);
        sq += __shfl_xor_sync(0xffffffffu, sq, o);
    }
    __shared__ float rs_[4], rq_[4];
    int lane = t & 31, w = t >> 5;
    if (lane == 0) { rs_[w] = s; rq_[w] = sq; }
    __syncthreads();
    s  = rs_[0] + rs_[1] + rs_[2] + rs_[3];
    sq = rq_[0] + rq_[1] + rq_[2] + rq_[3];
    float mu  = s * (1.0f / DIMD);
    float var = sq * (1.0f / DIMD) - mu * mu;
    float rstd = rsqrtf(var + 1e-5f);
    float4 gg = ((const float4*)g)[t];
    float4 bb = ((const float4*)be)[t];
    float4 o4;
    o4.x = (v.x - mu) * rstd * gg.x + bb.x;
    o4.y = (v.y - mu) * rstd * gg.y + bb.y;
    o4.z = (v.z - mu) * rstd * gg.z + bb.z;
    o4.w = (v.w - mu) * rstd * gg.w + bb.w;
    __nv_bfloat16 h0, l0, h1, l1, h2, l2, h3, l3;
    split_bf16(o4.x, h0, l0); split_bf16(o4.y, h1, l1);
    split_bf16(o4.z, h2, l2); split_bf16(o4.w, h3, l3);
    __nv_bfloat162 ph0; ph0.x = h0; ph0.y = h1;
    __nv_bfloat162 ph1; ph1.x = h2; ph1.y = h3;
    __nv_bfloat162 pl0; pl0.x = l0; pl0.y = l1;
    __nv_bfloat162 pl1; pl1.x = l2; pl1.y = l3;
    uint2 uh, ul;
    uh.x = *(uint32_t*)&ph0; uh.y = *(uint32_t*)&ph1;
    ul.x = *(uint32_t*)&pl0; ul.y = *(uint32_t*)&pl1;
    ((uint2*)(oh + (size_t)row * DIMD))[t] = uh;
    ((uint2*)(ol + (size_t)row * DIMD))[t] = ul;
}

// ---------------- tf32 tensor-core NN GEMM (2-stage pipelined) --------------
template <int EPI>
__global__ __launch_bounds__(256, 2) void gemm_tf32(
    const float* __restrict__ A, const float* __restrict__ Bm,
    const float* __restrict__ bias, const float* __restrict__ R,
    float* __restrict__ C, int M, int Ncols, int K)
{
    __shared__ float As[2][128][20];
    __shared__ float Bs[2][16][136];

    int tid = threadIdx.x, wid = tid >> 5, lane = tid & 31;
    int gid = lane >> 2, tg = lane & 3;
    int warpM = wid & 1, warpN = wid >> 1;
    int rowTile = blockIdx.y * 128, colTile = blockIdx.x * 128;

    int ar0 = tid >> 2, ac = (tid & 3) * 4;
    int br0 = tid >> 5, bc = (tid & 31) * 4;

    const float* Ap0 = A  + (size_t)(rowTile + ar0)      * K + ac;
    const float* Ap1 = A  + (size_t)(rowTile + ar0 + 64) * K + ac;
    const float* Bp0 = Bm + (size_t)br0       * Ncols + colTile + bc;
    const float* Bp1 = Bm + (size_t)(br0 + 8) * Ncols + colTile + bc;

    float acc[4][4][4] = {};

    float4 na0 = *(const float4*)Ap0;
    float4 na1 = *(const float4*)Ap1;
    float4 nb0 = *(const float4*)Bp0;
    float4 nb1 = *(const float4*)Bp1;
    *(float4*)&As[0][ar0     ][ac] = na0;
    *(float4*)&As[0][ar0 + 64][ac] = na1;
    *(float4*)&Bs[0][br0     ][bc] = nb0;
    *(float4*)&Bs[0][br0 + 8 ][bc] = nb1;
    __syncthreads();

    int nIter = K >> 4;
    int cur = 0;
    for (int it = 0; it < nIter; it++) {
        bool hasNext = (it + 1) < nIter;
        if (hasNext) {
            int koff = (it + 1) * 16;
            na0 = *(const float4*)(Ap0 + koff);
            na1 = *(const float4*)(Ap1 + koff);
            nb0 = *(const float4*)(Bp0 + (size_t)koff * Ncols);
            nb1 = *(const float4*)(Bp1 + (size_t)koff * Ncols);
        }

        #pragma unroll
        for (int ks = 0; ks < 16; ks += 8) {
            uint32_t af[4][4], bf[4][2];
            #pragma unroll
            for (int mt = 0; mt < 4; mt++) {
                int rb = warpM * 64 + mt * 16;
                af[mt][0] = __float_as_uint(As[cur][rb + gid    ][ks + tg    ]);
                af[mt][1] = __float_as_uint(As[cur][rb + gid + 8][ks + tg    ]);
                af[mt][2] = __float_as_uint(As[cur][rb + gid    ][ks + tg + 4]);
                af[mt][3] = __float_as_uint(As[cur][rb + gid + 8][ks + tg + 4]);
            }
            #pragma unroll
            for (int nt = 0; nt < 4; nt++) {
                int nb = warpN * 32 + nt * 8;
                bf[nt][0] = __float_as_uint(Bs[cur][ks + tg    ][nb + gid]);
                bf[nt][1] = __float_as_uint(Bs[cur][ks + tg + 4][nb + gid]);
            }
            #pragma unroll
            for (int mt = 0; mt < 4; mt++)
                #pragma unroll
                for (int nt = 0; nt < 4; nt++)
                    mma_tf32(acc[mt][nt], af[mt], bf[nt]);
        }

        if (hasNext) {
            int nxt = cur ^ 1;
            *(float4*)&As[nxt][ar0     ][ac] = na0;
            *(float4*)&As[nxt][ar0 + 64][ac] = na1;
            *(float4*)&Bs[nxt][br0     ][bc] = nb0;
            *(float4*)&Bs[nxt][br0 + 8 ][bc] = nb1;
        }
        __syncthreads();
        cur ^= 1;
    }

    #pragma unroll
    for (int mt = 0; mt < 4; mt++) {
        #pragma unroll
        for (int nt = 0; nt < 4; nt++) {
            int col  = colTile + warpN * 32 + nt * 8 + tg * 2;
            int row0 = rowTile + warpM * 64 + mt * 16 + gid;
            int row1 = row0 + 8;
            float2 o0 = make_float2(acc[mt][nt][0], acc[mt][nt][1]);
            float2 o1 = make_float2(acc[mt][nt][2], acc[mt][nt][3]);
            if (EPI >= 1) {
                float b0 = bias[col], b1 = bias[col + 1];
                o0.x += b0; o0.y += b1; o1.x += b0; o1.y += b1;
            }
            if (EPI == 3) {
                const float* r0p = R + (size_t)row0 * Ncols + col;
                const float* r1p = R + (size_t)row1 * Ncols + col;
                o0.x += r0p[0]; o0.y += r0p[1];
                o1.x += r1p[0]; o1.y += r1p[1];
            }
            *(float2*)(C + (size_t)row0 * Ncols + col) = o0;
            *(float2*)(C + (size_t)row1 * Ncols + col) = o1;
        }
    }
}

// ---------------- pre-split bf16x3 GEMM (2-stage pipelined) -----------------
// A_hi/A_lo: bf16 [M][K] row-major. B_hi/B_lo: bf16 [N][K] (transposed, K-contig).
// C = A @ B^T via hi*hi + hi*lo + lo*hi, fp32 accum.
// OUTBF: 0 -> fp32 C (EPI applies); 1 -> bf16 hi/lo outputs Ch/Cl (EPI applies first).
// EPI: 1=+bias, 2=+bias,gelu, 3=+bias,+residual
template <int EPI, int OUTBF>
__global__ __launch_bounds__(256, 2) void gemm_bf16p(
    const __nv_bfloat16* __restrict__ Ag_h, const __nv_bfloat16* __restrict__ Ag_l,
    const __nv_bfloat16* __restrict__ Bg_h, const __nv_bfloat16* __restrict__ Bg_l,
    const float* __restrict__ bias, const float* __restrict__ R,
    float* __restrict__ C, __nv_bfloat16* __restrict__ Ch, __nv_bfloat16* __restrict__ Cl,
    int M, int Ncols, int K)
{
    __shared__ uint32_t Ah[2][128][12], Al[2][128][12];
    __shared__ uint32_t Bh[2][128][12], Bl[2][128][12];

    int tid = threadIdx.x, wid = tid >> 5, lane = tid & 31;
    int gid = lane >> 2, tg = lane & 3;
    int warpM = wid & 1, warpN = wid >> 1;
    int rowTile = blockIdx.y * 128, colTile = blockIdx.x * 128;

    int lr = tid >> 1;            // 0..127: A row / B col
    int lk = (tid & 1) * 8;       // k element offset 0 or 8
    int lp = (tid & 1) * 4;       // kpair offset 0 or 4

    const __nv_bfloat16* ApH = Ag_h + (size_t)(rowTile + lr) * K + lk;
    const __nv_bfloat16* ApL = Ag_l + (size_t)(rowTile + lr) * K + lk;
    const __nv_bfloat16* BpH = Bg_h + (size_t)(colTile + lr) * K + lk;
    const __nv_bfloat16* BpL = Bg_l + (size_t)(colTile + lr) * K + lk;

    float acc[4][4][4] = {};

    uint4 vah = *(const uint4*)ApH;
    uint4 val = *(const uint4*)ApL;
    uint4 vbh = *(const uint4*)BpH;
    uint4 vbl = *(const uint4*)BpL;
    *(uint4*)&Ah[0][lr][lp] = vah;
    *(uint4*)&Al[0][lr][lp] = val;
    *(uint4*)&Bh[0][lr][lp] = vbh;
    *(uint4*)&Bl[0][lr][lp] = vbl;
    __syncthreads();

    int nIter = K >> 4;
    int cur = 0;
    for (int it = 0; it < nIter; it++) {
        bool hasNext = (it + 1) < nIter;
        if (hasNext) {
            int koff = (it + 1) * 16;
            vah = *(const uint4*)(ApH + koff);
            val = *(const uint4*)(ApL + koff);
            vbh = *(const uint4*)(BpH + koff);
            vbl = *(const uint4*)(BpL + koff);
        }

        uint32_t ah[4][4], al[4][4], bh[4][2], bl[4][2];
        #pragma unroll
        for (int mt = 0; mt < 4; mt++) {
            int rb = warpM * 64 + mt * 16;
            ah[mt][0] = Ah[cur][rb + gid    ][tg    ];
            ah[mt][1] = Ah[cur][rb + gid + 8][tg    ];
            ah[mt][2] = Ah[cur][rb + gid    ][tg + 4];
            ah[mt][3] = Ah[cur][rb + gid + 8][tg + 4];
            al[mt][0] = Al[cur][rb + gid    ][tg    ];
            al[mt][1] = Al[cur][rb + gid + 8][tg    ];
            al[mt][2] = Al[cur][rb + gid    ][tg + 4];
            al[mt][3] = Al[cur][rb + gid + 8][tg + 4];
        }
        #pragma unroll
        for (int nt = 0; nt < 4; nt++) {
            int nb = warpN * 32 + nt * 8;
            bh[nt][0] = Bh[cur][nb + gid][tg    ];
            bh[nt][1] = Bh[cur][nb + gid][tg + 4];
            bl[nt][0] = Bl[cur][nb + gid][tg    ];
            bl[nt][1] = Bl[cur][nb + gid][tg + 4];
        }
        #pragma unroll
        for (int mt = 0; mt < 4; mt++)
            #pragma unroll
            for (int nt = 0; nt < 4; nt++) {
                mma_bf16(acc[mt][nt], ah[mt], bh[nt]);
                mma_bf16(acc[mt][nt], ah[mt], bl[nt]);
                mma_bf16(acc[mt][nt], al[mt], bh[nt]);
            }

        if (hasNext) {
            int nxt = cur ^ 1;
            *(uint4*)&Ah[nxt][lr][lp] = vah;
            *(uint4*)&Al[nxt][lr][lp] = val;
            *(uint4*)&Bh[nxt][lr][lp] = vbh;
            *(uint4*)&Bl[nxt][lr][lp] = vbl;
        }
        __syncthreads();
        cur ^= 1;
    }

    #pragma unroll
    for (int mt = 0; mt < 4; mt++) {
        #pragma unroll
        for (int nt = 0; nt < 4; nt++) {
            int col  = colTile + warpN * 32 + nt * 8 + tg * 2;
            int row0 = rowTile + warpM * 64 + mt * 16 + gid;
            int row1 = row0 + 8;
            float2 o0 = make_float2(acc[mt][nt][0], acc[mt][nt][1]);
            float2 o1 = make_float2(acc[mt][nt][2], acc[mt][nt][3]);
            if (EPI >= 1) {
                float b0 = bias[col], b1 = bias[col + 1];
                o0.x += b0; o0.y += b1; o1.x += b0; o1.y += b1;
            }
            if (EPI == 2) {
                o0.x = gelu_exact(o0.x); o0.y = gelu_exact(o0.y);
                o1.x = gelu_exact(o1.x); o1.y = gelu_exact(o1.y);
            }
            if (EPI == 3) {
                const float* r0p = R + (size_t)row0 * Ncols + col;
                const float* r1p = R + (size_t)row1 * Ncols + col;
                o0.x += r0p[0]; o0.y += r0p[1];
                o1.x += r1p[0]; o1.y += r1p[1];
            }
            if constexpr (OUTBF) {
                __nv_bfloat16 h0, l0, h1, l1;
                split_bf16(o0.x, h0, l0); split_bf16(o0.y, h1, l1);
                __nv_bfloat162 ph; ph.x = h0; ph.y = h1;
                __nv_bfloat162 pl; pl.x = l0; pl.y = l1;
                *(__nv_bfloat162*)(Ch + (size_t)row0 * Ncols + col) = ph;
                *(__nv_bfloat162*)(Cl + (size_t)row0 * Ncols + col) = pl;
                split_bf16(o1.x, h0, l0); split_bf16(o1.y, h1, l1);
                ph.x = h0; ph.y = h1; pl.x = l0; pl.y = l1;
                *(__nv_bfloat162*)(Ch + (size_t)row1 * Ncols + col) = ph;
                *(__nv_bfloat162*)(Cl + (size_t)row1 * Ncols + col) = pl;
            } else {
                *(float2*)(C + (size_t)row0 * Ncols + col) = o0;
                *(float2*)(C + (size_t)row1 * Ncols + col) = o1;
            }
        }
    }
}

// ---------------- Flash attention (tf32 MMA, online softmax) ----------------
#define FLDS 68
#define FSM_BYTES (3 * 64 * FLDS * 4)

__global__ __launch_bounds__(128, 3) void flash_tf32(
    const float* __restrict__ qp, const float* __restrict__ kp,
    const float* __restrict__ vp, float* __restrict__ att)
{
    extern __shared__ float sm_[];
    float* Ks = sm_;
    float* Vs = sm_ + 64 * FLDS;
    float* Ps = sm_ + 2 * 64 * FLDS;

    int z = blockIdx.y, b = z >> 3, hh = z & 7;
    const float* Q = qp + (size_t)b * SEQ * DIMD + hh * HD;
    const float* K = kp + (size_t)b * SEQ * DIMD + hh * HD;
    const float* V = vp + (size_t)b * SEQ * DIMD + hh * HD;
    float* O = att + (size_t)b * SEQ * DIMD + hh * HD;
    int q0 = blockIdx.x * 64;

    int tid = threadIdx.x, wid = tid >> 5, lane = tid & 31;
    int gid = lane >> 2, tg = lane & 3;
    int rb = wid * 16;

    for (int idx = tid; idx < 64 * 16; idx += 128) {
        int r = idx >> 4, c4 = (idx & 15) * 4;
        float4 a = *(const float4*)(Q + (size_t)(q0 + r) * DIMD + c4);
        a.x *= 0.125f; a.y *= 0.125f; a.z *= 0.125f; a.w *= 0.125f;
        *(float4*)&Ps[r * FLDS + c4] = a;
    }
    __syncthreads();
    uint32_t qf[8][4];
    #pragma unroll
    for (int ki = 0; ki < 8; ki++) {
        int ks = ki * 8;
        qf[ki][0] = __float_as_uint(Ps[(rb + gid    ) * FLDS + ks + tg    ]);
        qf[ki][1] = __float_as_uint(Ps[(rb + gid + 8) * FLDS + ks + tg    ]);
        qf[ki][2] = __float_as_uint(Ps[(rb + gid    ) * FLDS + ks + tg + 4]);
        qf[ki][3] = __float_as_uint(Ps[(rb + gid + 8) * FLDS + ks + tg + 4]);
    }
    __syncthreads();

    float m0 = -1e30f, m1 = -1e30f, l0 = 0.0f, l1 = 0.0f;
    float o[8][4] = {};

    for (int t0 = 0; t0 < SEQ; t0 += 64) {
        for (int idx = tid; idx < 64 * 16; idx += 128) {
            int r = idx >> 4, c4 = (idx & 15) * 4;
            *(float4*)&Ks[r * FLDS + c4] =
                *(const float4*)(K + (size_t)(t0 + r) * DIMD + c4);
            *(float4*)&Vs[r * FLDS + c4] =
                *(const float4*)(V + (size_t)(t0 + r) * DIMD + c4);
        }
        __syncthreads();

        float s[8][4] = {};
        #pragma unroll
        for (int ki = 0; ki < 8; ki++) {
            int ks = ki * 8;
            #pragma unroll
            for (int nt = 0; nt < 8; nt++) {
                uint32_t bf[2];
                bf[0] = __float_as_uint(Ks[(nt * 8 + gid) * FLDS + ks + tg    ]);
                bf[1] = __float_as_uint(Ks[(nt * 8 + gid) * FLDS + ks + tg + 4]);
                mma_tf32(s[nt], qf[ki], bf);
            }
        }

        float tm0 = -1e30f, tm1 = -1e30f;
        #pragma unroll
        for (int nt = 0; nt < 8; nt++) {
            tm0 = fmaxf(tm0, fmaxf(s[nt][0], s[nt][1]));
            tm1 = fmaxf(tm1, fmaxf(s[nt][2], s[nt][3]));
        }
        tm0 = fmaxf(tm0, __shfl_xor_sync(0xffffffffu, tm0, 1));
        tm0 = fmaxf(tm0, __shfl_xor_sync(0xffffffffu, tm0, 2));
        tm1 = fmaxf(tm1, __shfl_xor_sync(0xffffffffu, tm1, 1));
        tm1 = fmaxf(tm1, __shfl_xor_sync(0xffffffffu, tm1, 2));
        float nm0 = fmaxf(m0, tm0), nm1 = fmaxf(m1, tm1);
        float r0 = __expf(m0 - nm0), r1 = __expf(m1 - nm1);
        float sum0 = 0.0f, sum1 = 0.0f;
        #pragma unroll
        for (int nt = 0; nt < 8; nt++) {
            s[nt][0] = __expf(s[nt][0] - nm0);
            s[nt][1] = __expf(s[nt][1] - nm0);
            s[nt][2] = __expf(s[nt][2] - nm1);
            s[nt][3] = __expf(s[nt][3] - nm1);
            sum0 += s[nt][0] + s[nt][1];
            sum1 += s[nt][2] + s[nt][3];
        }
        sum0 += __shfl_xor_sync(0xffffffffu, sum0, 1);
        sum0 += __shfl_xor_sync(0xffffffffu, sum0, 2);
        sum1 += __shfl_xor_sync(0xffffffffu, sum1, 1);
        sum1 += __shfl_xor_sync(0xffffffffu, sum1, 2);
        l0 = l0 * r0 + sum0;
        l1 = l1 * r1 + sum1;
        m0 = nm0; m1 = nm1;
        #pragma unroll
        for (int nt = 0; nt < 8; nt++) {
            o[nt][0] *= r0; o[nt][1] *= r0;
            o[nt][2] *= r1; o[nt][3] *= r1;
        }

        #pragma unroll
        for (int nt = 0; nt < 8; nt++) {
            *(float2*)&Ps[(rb + gid    ) * FLDS + nt * 8 + tg * 2] =
                make_float2(s[nt][0], s[nt][1]);
            *(float2*)&Ps[(rb + gid + 8) * FLDS + nt * 8 + tg * 2] =
                make_float2(s[nt][2], s[nt][3]);
        }
        __syncthreads();

        #pragma unroll
        for (int ki = 0; ki < 8; ki++) {
            int ks = ki * 8;
            uint32_t af[4];
            af[0] = __float_as_uint(Ps[(rb + gid    ) * FLDS + ks + tg    ]);
            af[1] = __float_as_uint(Ps[(rb + gid + 8) * FLDS + ks + tg    ]);
            af[2] = __float_as_uint(Ps[(rb + gid    ) * FLDS + ks + tg + 4]);
            af[3] = __float_as_uint(Ps[(rb + gid + 8) * FLDS + ks + tg + 4]);
            #pragma unroll
            for (int nt = 0; nt < 8; nt++) {
                uint32_t bf[2];
                bf[0] = __float_as_uint(Vs[(ks + tg    ) * FLDS + nt * 8 + gid]);
                bf[1] = __float_as_uint(Vs[(ks + tg + 4) * FLDS + nt * 8 + gid]);
                mma_tf32(o[nt], af, bf);
            }
        }
        __syncthreads();
    }

    float inv0 = 1.0f / l0, inv1 = 1.0f / l1;
    int row0 = q0 + rb + gid, row1 = row0 + 8;
    #pragma unroll
    for (int nt = 0; nt < 8; nt++) {
        int col = nt * 8 + tg * 2;
        *(float2*)(O + (size_t)row0 * DIMD + col) =
            make_float2(o[nt][0] * inv0, o[nt][1] * inv0);
        *(float2*)(O + (size_t)row1 * DIMD + col) =
            make_float2(o[nt][2] * inv1, o[nt][3] * inv1);
    }
}

// ---------------- launch ----------------------------------------------------
extern "C" void kernel_launch(void* const* d_in, const int* in_sizes, int n_in,
                              void* d_out, int out_size) {
    const float* x   = (const float*)d_in[0];
    const float* Wq  = (const float*)d_in[1];
    const float* Wk  = (const float*)d_in[2];
    const float* Wv  = (const float*)d_in[3];
    const float* Wo  = (const float*)d_in[4];
    const float* bo  = (const float*)d_in[5];
    const float* W1  = (const float*)d_in[6];
    const float* b1  = (const float*)d_in[7];
    const float* W2  = (const float*)d_in[8];
    const float* b2  = (const float*)d_in[9];
    const float* g1  = (const float*)d_in[10];
    const float* be1 = (const float*)d_in[11];
    const float* g2  = (const float*)d_in[12];
    const float* be2 = (const float*)d_in[13];
    float* out = (float*)d_out;

    float *h, *q, *k, *v, *att, *xm;
    __nv_bfloat16 *h2h, *h2l, *ffh, *ffl, *w1h, *w1l, *w2h, *w2l;
    cudaGetSymbolAddress((void**)&h,   g_h);
    cudaGetSymbolAddress((void**)&q,   g_q);
    cudaGetSymbolAddress((void**)&k,   g_k);
    cudaGetSymbolAddress((void**)&v,   g_v);
    cudaGetSymbolAddress((void**)&att, g_att);
    cudaGetSymbolAddress((void**)&xm,  g_xm);
    cudaGetSymbolAddress((void**)&h2h, g_h2h);
    cudaGetSymbolAddress((void**)&h2l, g_h2l);
    cudaGetSymbolAddress((void**)&ffh, g_ffh);
    cudaGetSymbolAddress((void**)&ffl, g_ffl);
    cudaGetSymbolAddress((void**)&w1h, g_w1h);
    cudaGetSymbolAddress((void**)&w1l, g_w1l);
    cudaGetSymbolAddress((void**)&w2h, g_w2h);
    cudaGetSymbolAddress((void**)&w2l, g_w2l);

    cudaFuncSetAttribute(flash_tf32,
                         cudaFuncAttributeMaxDynamicSharedMemorySize, FSM_BYTES);

    dim3 gProj(DIMD / 128, BN_TOK / 128);       // (4, 64)
    dim3 gMlp(MLPD / 128, BN_TOK / 128);        // (16, 64)

    // 0) weight transpose + bf16 split (runs concurrently with LN/QKV chain)
    wsplit_kernel<<<dim3(MLPD / 32, DIMD / 32), dim3(32, 8)>>>(W1, w1h, w1l, DIMD, MLPD);
    wsplit_kernel<<<dim3(DIMD / 32, MLPD / 32), dim3(32, 8)>>>(W2, w2h, w2l, MLPD, DIMD);
    // 1) h = LN(x; g1, be1)
    ln_kernel<<<BN_TOK, 128>>>(x, g1, be1, h);
    // 2) q, k, v projections (single-pass tf32)
    gemm_tf32<0><<<gProj, 256>>>(h, Wq, nullptr, nullptr, q, BN_TOK, DIMD, DIMD);
    gemm_tf32<0><<<gProj, 256>>>(h, Wk, nullptr, nullptr, k, BN_TOK, DIMD, DIMD);
    gemm_tf32<0><<<gProj, 256>>>(h, Wv, nullptr, nullptr, v, BN_TOK, DIMD, DIMD);
    // 3-5) fused flash attention
    flash_tf32<<<dim3(SEQ / 64, BATCH * HEADS), 128, FSM_BYTES>>>(q, k, v, att);
    // 6) xm = x + att @ Wo + bo
    gemm_tf32<3><<<gProj, 256>>>(att, Wo, bo, x, xm, BN_TOK, DIMD, DIMD);
    // 7) h2 = LN(xm; g2, be2) -> pre-split bf16 hi/lo
    ln_bf16_kernel<<<BN_TOK, 128>>>(xm, g2, be2, h2h, h2l);
    // 8) ff = gelu(h2 @ W1 + b1) -> pre-split bf16 hi/lo
    gemm_bf16p<2, 1><<<gMlp, 256>>>(h2h, h2l, w1h, w1l, b1, nullptr,
                                    nullptr, ffh, ffl, BN_TOK, MLPD, DIMD);
    // 9) out = xm + ff @ W2 + b2  (fp32 out)
    gemm_bf16p<3, 0><<<gProj, 256>>>(ffh, ffl, w2h, w2l, b2, xm,
                                     out, nullptr, nullptr, BN_TOK, DIMD, MLPD);
}

// round 13
// speedup vs baseline: 1.0702x; 1.0497x over previous
#include <cuda_runtime.h>
#include <cuda_bf16.h>
#include <math.h>
#include <stdint.h>

#define DIMD   512
#define HEADS  8
#define HD     64
#define MLPD   2048
#define BATCH  2
#define SEQ    4096
#define BN_TOK 8192   // BATCH*SEQ

// ---------------- scratch (static device arrays; no allocation) -------------
__device__ float g_h  [(size_t)BN_TOK * DIMD];
__device__ float g_q  [(size_t)BN_TOK * DIMD];
__device__ float g_k  [(size_t)BN_TOK * DIMD];
__device__ float g_v  [(size_t)BN_TOK * DIMD];
__device__ float g_att[(size_t)BN_TOK * DIMD];
__device__ float g_xm [(size_t)BN_TOK * DIMD];
__device__ __nv_bfloat16 g_h2h[(size_t)BN_TOK * DIMD];
__device__ __nv_bfloat16 g_h2l[(size_t)BN_TOK * DIMD];
__device__ __nv_bfloat16 g_ffh[(size_t)BN_TOK * MLPD];
__device__ __nv_bfloat16 g_ffl[(size_t)BN_TOK * MLPD];
__device__ __nv_bfloat16 g_w1h[(size_t)MLPD * DIMD], g_w1l[(size_t)MLPD * DIMD];
__device__ __nv_bfloat16 g_w2h[(size_t)DIMD * MLPD], g_w2l[(size_t)DIMD * MLPD];

__device__ __forceinline__ float gelu_exact(float x) {
    return 0.5f * x * (1.0f + erff(x * 0.70710678118654752440f));
}
__device__ __forceinline__ uint32_t pack2_bf16(float a, float b) {
    __nv_bfloat162 t = __floats2bfloat162_rn(a, b);
    return *reinterpret_cast<uint32_t*>(&t);
}
__device__ __forceinline__ void split_bf16(float x, __nv_bfloat16& hi, __nv_bfloat16& lo) {
    hi = __float2bfloat16_rn(x);
    lo = __float2bfloat16_rn(x - __bfloat162float(hi));
}
__device__ __forceinline__ uint32_t smem_u32(const void* p) {
    uint32_t a;
    asm("{ .reg .u64 t; cvta.to.shared.u64 t, %1; cvt.u32.u64 %0, t; }" : "=r"(a) : "l"(p));
    return a;
}

// ---------------- mma.sync -------------------------------------------------
__device__ __forceinline__ void mma_tf32(float* c, const uint32_t* a, const uint32_t* b) {
    asm volatile(
        "mma.sync.aligned.m16n8k8.row.col.f32.tf32.tf32.f32 "
        "{%0,%1,%2,%3},{%4,%5,%6,%7},{%8,%9},{%0,%1,%2,%3};\n"
        : "+f"(c[0]), "+f"(c[1]), "+f"(c[2]), "+f"(c[3])
        : "r"(a[0]), "r"(a[1]), "r"(a[2]), "r"(a[3]), "r"(b[0]), "r"(b[1]));
}
__device__ __forceinline__ void mma_bf16(float* c, const uint32_t* a, const uint32_t* b) {
    asm volatile(
        "mma.sync.aligned.m16n8k16.row.col.f32.bf16.bf16.f32 "
        "{%0,%1,%2,%3},{%4,%5,%6,%7},{%8,%9},{%0,%1,%2,%3};\n"
        : "+f"(c[0]), "+f"(c[1]), "+f"(c[2]), "+f"(c[3])
        : "r"(a[0]), "r"(a[1]), "r"(a[2]), "r"(a[3]), "r"(b[0]), "r"(b[1]));
}

// ---------------- cp.async -------------------------------------------------
__device__ __forceinline__ void cp_async16(uint32_t dst, const void* src) {
    asm volatile("cp.async.cg.shared.global [%0], [%1], 16;" :: "r"(dst), "l"(src));
}
#define CP_COMMIT() asm volatile("cp.async.commit_group;" ::: "memory")
#define CP_WAIT1()  asm volatile("cp.async.wait_group 1;" ::: "memory")

// ---------------- weight transpose + split: W[K][N] -> T_hi/lo[N][K] --------
__global__ void wsplit_kernel(const float* __restrict__ W,
                              __nv_bfloat16* __restrict__ Th,
                              __nv_bfloat16* __restrict__ Tl,
                              int K, int N) {
    __shared__ float tile[32][33];
    int kb = blockIdx.y * 32, nb = blockIdx.x * 32;
    int tx = threadIdx.x, ty = threadIdx.y;   // 32 x 8
    #pragma unroll
    for (int i = 0; i < 32; i += 8)
        tile[ty + i][tx] = W[(size_t)(kb + ty + i) * N + nb + tx];
    __syncthreads();
    #pragma unroll
    for (int i = 0; i < 32; i += 8) {
        float v = tile[tx][ty + i];
        __nv_bfloat16 hi, lo;
        split_bf16(v, hi, lo);
        size_t o = (size_t)(nb + ty + i) * K + kb + tx;
        Th[o] = hi;
        Tl[o] = lo;
    }
}

// ---------------- LayerNorm (fp32 out) --------------------------------------
__global__ void ln_kernel(const float* __restrict__ x, const float* __restrict__ g,
                          const float* __restrict__ be, float* __restrict__ out) {
    int row = blockIdx.x;
    int t = threadIdx.x;
    const float4* xr = (const float4*)(x + (size_t)row * DIMD);
    float4 v = xr[t];
    float s  = v.x + v.y + v.z + v.w;
    float sq = v.x * v.x + v.y * v.y + v.z * v.z + v.w * v.w;
    #pragma unroll
    for (int o = 16; o > 0; o >>= 1) {
        s  += __shfl_xor_sync(0xffffffffu, s,  o);
        sq += __shfl_xor_sync(0xffffffffu, sq, o);
    }
    __shared__ float rs_[4], rq_[4];
    int lane = t & 31, w = t >> 5;
    if (lane == 0) { rs_[w] = s; rq_[w] = sq; }
    __syncthreads();
    s  = rs_[0] + rs_[1] + rs_[2] + rs_[3];
    sq = rq_[0] + rq_[1] + rq_[2] + rq_[3];
    float mu  = s * (1.0f / DIMD);
    float var = sq * (1.0f / DIMD) - mu * mu;
    float rstd = rsqrtf(var + 1e-5f);
    float4 gg = ((const float4*)g)[t];
    float4 bb = ((const float4*)be)[t];
    float4 o4;
    o4.x = (v.x - mu) * rstd * gg.x + bb.x;
    o4.y = (v.y - mu) * rstd * gg.y + bb.y;
    o4.z = (v.z - mu) * rstd * gg.z + bb.z;
    o4.w = (v.w - mu) * rstd * gg.w + bb.w;
    ((float4*)(out + (size_t)row * DIMD))[t] = o4;
}

// ---------------- LayerNorm (bf16 hi/lo out) --------------------------------
__global__ void ln_bf16_kernel(const float* __restrict__ x, const float* __restrict__ g,
                               const float* __restrict__ be,
                               __nv_bfloat16* __restrict__ oh,
                               __nv_bfloat16* __restrict__ ol) {
    int row = blockIdx.x;
    int t = threadIdx.x;
    const float4* xr = (const float4*)(x + (size_t)row * DIMD);
    float4 v = xr[t];
    float s  = v.x + v.y + v.z + v.w;
    float sq = v.x * v.x + v.y * v.y + v.z * v.z + v.w * v.w;
    #pragma unroll
    for (int o = 16; o > 0; o >>= 1) {
        s  += __shfl_xor_sync(0xffffffffu, s,  o);
        sq += __shfl_xor_sync(0xffffffffu, sq, o);
    }
    __shared__ float rs_[4], rq_[4];
    int lane = t & 31, w = t >> 5;
    if (lane == 0) { rs_[w] = s; rq_[w] = sq; }
    __syncthreads();
    s  = rs_[0] + rs_[1] + rs_[2] + rs_[3];
    sq = rq_[0] + rq_[1] + rq_[2] + rq_[3];
    float mu  = s * (1.0f / DIMD);
    float var = sq * (1.0f / DIMD) - mu * mu;
    float rstd = rsqrtf(var + 1e-5f);
    float4 gg = ((const float4*)g)[t];
    float4 bb = ((const float4*)be)[t];
    float4 o4;
    o4.x = (v.x - mu) * rstd * gg.x + bb.x;
    o4.y = (v.y - mu) * rstd * gg.y + bb.y;
    o4.z = (v.z - mu) * rstd * gg.z + bb.z;
    o4.w = (v.w - mu) * rstd * gg.w + bb.w;
    __nv_bfloat16 h0, l0, h1, l1, h2, l2, h3, l3;
    split_bf16(o4.x, h0, l0); split_bf16(o4.y, h1, l1);
    split_bf16(o4.z, h2, l2); split_bf16(o4.w, h3, l3);
    uint2 uh, ul;
    uh.x = pack2_bf16(__bfloat162float(h0), __bfloat162float(h1));
    uh.y = pack2_bf16(__bfloat162float(h2), __bfloat162float(h3));
    ul.x = pack2_bf16(__bfloat162float(l0), __bfloat162float(l1));
    ul.y = pack2_bf16(__bfloat162float(l2), __bfloat162float(l3));
    ((uint2*)(oh + (size_t)row * DIMD))[t] = uh;
    ((uint2*)(ol + (size_t)row * DIMD))[t] = ul;
}

// ---------------- tf32 GEMM, cp.async 3-stage pipeline ----------------------
// C[M,N] = A[M,K] @ B[K,N] (+epilogue). BM=128, BN=128, BK=16, 256 threads.
// dynamic smem: As stage 10240B (128x20 f32), Bs stage 8704B (16x136 f32).
#define TF_AS(st)  ((st) * 10240)
#define TF_BS(st)  (30720 + (st) * 8704)
#define TF_SMEM    56832

template <int EPI>
__global__ __launch_bounds__(256, 2) void gemm_tf32(
    const float* __restrict__ A, const float* __restrict__ Bm,
    const float* __restrict__ bias, const float* __restrict__ R,
    float* __restrict__ C, int M, int Ncols, int K)
{
    extern __shared__ char dsm[];
    uint32_t sb = smem_u32(dsm);

    int tid = threadIdx.x, wid = tid >> 5, lane = tid & 31;
    int gid = lane >> 2, tg = lane & 3;
    int warpM = wid & 1, warpN = wid >> 1;
    int rowTile = blockIdx.y * 128, colTile = blockIdx.x * 128;

    int ar0 = tid >> 2, ac = (tid & 3) * 4;
    int br0 = tid >> 5, bc = (tid & 31) * 4;

    const float* Ap0 = A  + (size_t)(rowTile + ar0)      * K + ac;
    const float* Ap1 = A  + (size_t)(rowTile + ar0 + 64) * K + ac;
    const float* Bp0 = Bm + (size_t)br0       * Ncols + colTile + bc;
    const float* Bp1 = Bm + (size_t)(br0 + 8) * Ncols + colTile + bc;

    uint32_t dA0 = (uint32_t)(ar0 * 20 + ac) * 4;
    uint32_t dA1 = (uint32_t)((ar0 + 64) * 20 + ac) * 4;
    uint32_t dB0 = (uint32_t)(br0 * 136 + bc) * 4;
    uint32_t dB1 = (uint32_t)((br0 + 8) * 136 + bc) * 4;

    float acc[4][4][4] = {};
    int nIter = K >> 4;

    // prologue: stages 0, 1
    #pragma unroll
    for (int s = 0; s < 2; s++) {
        int k0 = s * 16;
        cp_async16(sb + TF_AS(s) + dA0, Ap0 + k0);
        cp_async16(sb + TF_AS(s) + dA1, Ap1 + k0);
        cp_async16(sb + TF_BS(s) + dB0, Bp0 + (size_t)k0 * Ncols);
        cp_async16(sb + TF_BS(s) + dB1, Bp1 + (size_t)k0 * Ncols);
        CP_COMMIT();
    }

    for (int it = 0; it < nIter; it++) {
        CP_WAIT1();
        __syncthreads();
        int nx = it + 2;
        if (nx < nIter) {
            int st = nx - (nx / 3) * 3;
            int k0 = nx * 16;
            cp_async16(sb + TF_AS(st) + dA0, Ap0 + k0);
            cp_async16(sb + TF_AS(st) + dA1, Ap1 + k0);
            cp_async16(sb + TF_BS(st) + dB0, Bp0 + (size_t)k0 * Ncols);
            cp_async16(sb + TF_BS(st) + dB1, Bp1 + (size_t)k0 * Ncols);
        }
        CP_COMMIT();

        int cur = it - (it / 3) * 3;
        const float* Asc = (const float*)(dsm + TF_AS(cur));
        const float* Bsc = (const float*)(dsm + TF_BS(cur));

        #pragma unroll
        for (int ks = 0; ks < 16; ks += 8) {
            uint32_t af[4][4], bf[4][2];
            #pragma unroll
            for (int mt = 0; mt < 4; mt++) {
                int rb = warpM * 64 + mt * 16;
                af[mt][0] = __float_as_uint(Asc[(rb + gid    ) * 20 + ks + tg    ]);
                af[mt][1] = __float_as_uint(Asc[(rb + gid + 8) * 20 + ks + tg    ]);
                af[mt][2] = __float_as_uint(Asc[(rb + gid    ) * 20 + ks + tg + 4]);
                af[mt][3] = __float_as_uint(Asc[(rb + gid + 8) * 20 + ks + tg + 4]);
            }
            #pragma unroll
            for (int nt = 0; nt < 4; nt++) {
                int nb = warpN * 32 + nt * 8;
                bf[nt][0] = __float_as_uint(Bsc[(ks + tg    ) * 136 + nb + gid]);
                bf[nt][1] = __float_as_uint(Bsc[(ks + tg + 4) * 136 + nb + gid]);
            }
            #pragma unroll
            for (int mt = 0; mt < 4; mt++)
                #pragma unroll
                for (int nt = 0; nt < 4; nt++)
                    mma_tf32(acc[mt][nt], af[mt], bf[nt]);
        }
    }

    #pragma unroll
    for (int mt = 0; mt < 4; mt++) {
        #pragma unroll
        for (int nt = 0; nt < 4; nt++) {
            int col  = colTile + warpN * 32 + nt * 8 + tg * 2;
            int row0 = rowTile + warpM * 64 + mt * 16 + gid;
            int row1 = row0 + 8;
            float2 o0 = make_float2(acc[mt][nt][0], acc[mt][nt][1]);
            float2 o1 = make_float2(acc[mt][nt][2], acc[mt][nt][3]);
            if (EPI >= 1) {
                float b0 = bias[col], b1 = bias[col + 1];
                o0.x += b0; o0.y += b1; o1.x += b0; o1.y += b1;
            }
            if (EPI == 3) {
                const float* r0p = R + (size_t)row0 * Ncols + col;
                const float* r1p = R + (size_t)row1 * Ncols + col;
                o0.x += r0p[0]; o0.y += r0p[1];
                o1.x += r1p[0]; o1.y += r1p[1];
            }
            *(float2*)(C + (size_t)row0 * Ncols + col) = o0;
            *(float2*)(C + (size_t)row1 * Ncols + col) = o1;
        }
    }
}

// ---------------- pre-split bf16x3 GEMM, cp.async 3-stage -------------------
// A_hi/A_lo bf16 [M][K]; B_hi/B_lo bf16 [N][K]. C = A @ B^T (hh + hl + lh).
// BM=128, BN=128, BK=16. Smem per stage per array: 128 rows x 12 u32 (48B rows).
#define BF_AH(st)  ((st) * 6144)
#define BF_AL(st)  (18432 + (st) * 6144)
#define BF_BH(st)  (36864 + (st) * 6144)
#define BF_BL(st)  (55296 + (st) * 6144)
#define BF_SMEM    73728

template <int EPI, int OUTBF>
__global__ __launch_bounds__(256, 2) void gemm_bf16p(
    const __nv_bfloat16* __restrict__ Agh, const __nv_bfloat16* __restrict__ Agl,
    const __nv_bfloat16* __restrict__ Bgh, const __nv_bfloat16* __restrict__ Bgl,
    const float* __restrict__ bias, const float* __restrict__ R,
    float* __restrict__ C, __nv_bfloat16* __restrict__ Ch, __nv_bfloat16* __restrict__ Cl,
    int M, int Ncols, int K)
{
    extern __shared__ char dsm[];
    uint32_t sb = smem_u32(dsm);

    int tid = threadIdx.x, wid = tid >> 5, lane = tid & 31;
    int gid = lane >> 2, tg = lane & 3;
    int warpM = wid & 1, warpN = wid >> 1;
    int rowTile = blockIdx.y * 128, colTile = blockIdx.x * 128;

    int lr = tid >> 1;              // 0..127 (A row / B col)
    int lk = (tid & 1) * 8;         // element offset (8 bf16 = 16B)
    uint32_t dOff = (uint32_t)lr * 48 + (tid & 1) * 16;

    const __nv_bfloat16* ApH = Agh + (size_t)(rowTile + lr) * K + lk;
    const __nv_bfloat16* ApL = Agl + (size_t)(rowTile + lr) * K + lk;
    const __nv_bfloat16* BpH = Bgh + (size_t)(colTile + lr) * K + lk;
    const __nv_bfloat16* BpL = Bgl + (size_t)(colTile + lr) * K + lk;

    float acc[4][4][4] = {};
    int nIter = K >> 4;

    #pragma unroll
    for (int s = 0; s < 2; s++) {
        int k0 = s * 16;
        cp_async16(sb + BF_AH(s) + dOff, ApH + k0);
        cp_async16(sb + BF_AL(s) + dOff, ApL + k0);
        cp_async16(sb + BF_BH(s) + dOff, BpH + k0);
        cp_async16(sb + BF_BL(s) + dOff, BpL + k0);
        CP_COMMIT();
    }

    for (int it = 0; it < nIter; it++) {
        CP_WAIT1();
        __syncthreads();
        int nx = it + 2;
        if (nx < nIter) {
            int st = nx - (nx / 3) * 3;
            int k0 = nx * 16;
            cp_async16(sb + BF_AH(st) + dOff, ApH + k0);
            cp_async16(sb + BF_AL(st) + dOff, ApL + k0);
            cp_async16(sb + BF_BH(st) + dOff, BpH + k0);
            cp_async16(sb + BF_BL(st) + dOff, BpL + k0);
        }
        CP_COMMIT();

        int cur = it - (it / 3) * 3;
        const uint32_t* AhS = (const uint32_t*)(dsm + BF_AH(cur));
        const uint32_t* AlS = (const uint32_t*)(dsm + BF_AL(cur));
        const uint32_t* BhS = (const uint32_t*)(dsm + BF_BH(cur));
        const uint32_t* BlS = (const uint32_t*)(dsm + BF_BL(cur));

        uint32_t ah[4][4], al[4][4], bh[4][2], bl[4][2];
        #pragma unroll
        for (int mt = 0; mt < 4; mt++) {
            int rb = warpM * 64 + mt * 16;
            ah[mt][0] = AhS[(rb + gid    ) * 12 + tg    ];
            ah[mt][1] = AhS[(rb + gid + 8) * 12 + tg    ];
            ah[mt][2] = AhS[(rb + gid    ) * 12 + tg + 4];
            ah[mt][3] = AhS[(rb + gid + 8) * 12 + tg + 4];
            al[mt][0] = AlS[(rb + gid    ) * 12 + tg    ];
            al[mt][1] = AlS[(rb + gid + 8) * 12 + tg    ];
            al[mt][2] = AlS[(rb + gid    ) * 12 + tg + 4];
            al[mt][3] = AlS[(rb + gid + 8) * 12 + tg + 4];
        }
        #pragma unroll
        for (int nt = 0; nt < 4; nt++) {
            int nb = warpN * 32 + nt * 8;
            bh[nt][0] = BhS[(nb + gid) * 12 + tg    ];
            bh[nt][1] = BhS[(nb + gid) * 12 + tg + 4];
            bl[nt][0] = BlS[(nb + gid) * 12 + tg    ];
            bl[nt][1] = BlS[(nb + gid) * 12 + tg + 4];
        }
        #pragma unroll
        for (int mt = 0; mt < 4; mt++)
            #pragma unroll
            for (int nt = 0; nt < 4; nt++) {
                mma_bf16(acc[mt][nt], ah[mt], bh[nt]);
                mma_bf16(acc[mt][nt], ah[mt], bl[nt]);
                mma_bf16(acc[mt][nt], al[mt], bh[nt]);
            }
    }

    #pragma unroll
    for (int mt = 0; mt < 4; mt++) {
        #pragma unroll
        for (int nt = 0; nt < 4; nt++) {
            int col  = colTile + warpN * 32 + nt * 8 + tg * 2;
            int row0 = rowTile + warpM * 64 + mt * 16 + gid;
            int row1 = row0 + 8;
            float2 o0 = make_float2(acc[mt][nt][0], acc[mt][nt][1]);
            float2 o1 = make_float2(acc[mt][nt][2], acc[mt][nt][3]);
            if (EPI >= 1) {
                float b0 = bias[col], b1 = bias[col + 1];
                o0.x += b0; o0.y += b1; o1.x += b0; o1.y += b1;
            }
            if (EPI == 2) {
                o0.x = gelu_exact(o0.x); o0.y = gelu_exact(o0.y);
                o1.x = gelu_exact(o1.x); o1.y = gelu_exact(o1.y);
            }
            if (EPI == 3) {
                const float* r0p = R + (size_t)row0 * Ncols + col;
                const float* r1p = R + (size_t)row1 * Ncols + col;
                o0.x += r0p[0]; o0.y += r0p[1];
                o1.x += r1p[0]; o1.y += r1p[1];
            }
            if constexpr (OUTBF) {
                __nv_bfloat16 h0, l0, h1, l1;
                split_bf16(o0.x, h0, l0); split_bf16(o0.y, h1, l1);
                __nv_bfloat162 ph; ph.x = h0; ph.y = h1;
                __nv_bfloat162 pl; pl.x = l0; pl.y = l1;
                *(__nv_bfloat162*)(Ch + (size_t)row0 * Ncols + col) = ph;
                *(__nv_bfloat162*)(Cl + (size_t)row0 * Ncols + col) = pl;
                split_bf16(o1.x, h0, l0); split_bf16(o1.y, h1, l1);
                ph.x = h0; ph.y = h1; pl.x = l0; pl.y = l1;
                *(__nv_bfloat162*)(Ch + (size_t)row1 * Ncols + col) = ph;
                *(__nv_bfloat162*)(Cl + (size_t)row1 * Ncols + col) = pl;
            } else {
                *(float2*)(C + (size_t)row0 * Ncols + col) = o0;
                *(float2*)(C + (size_t)row1 * Ncols + col) = o1;
            }
        }
    }
}

// ---------------- Flash attention (tf32 MMA, online softmax) ----------------
#define FLDS 68
#define FSM_BYTES (3 * 64 * FLDS * 4)

__global__ __launch_bounds__(128, 3) void flash_tf32(
    const float* __restrict__ qp, const float* __restrict__ kp,
    const float* __restrict__ vp, float* __restrict__ att)
{
    extern __shared__ float sm_[];
    float* Ks = sm_;
    float* Vs = sm_ + 64 * FLDS;
    float* Ps = sm_ + 2 * 64 * FLDS;

    int z = blockIdx.y, b = z >> 3, hh = z & 7;
    const float* Q = qp + (size_t)b * SEQ * DIMD + hh * HD;
    const float* K = kp + (size_t)b * SEQ * DIMD + hh * HD;
    const float* V = vp + (size_t)b * SEQ * DIMD + hh * HD;
    float* O = att + (size_t)b * SEQ * DIMD + hh * HD;
    int q0 = blockIdx.x * 64;

    int tid = threadIdx.x, wid = tid >> 5, lane = tid & 31;
    int gid = lane >> 2, tg = lane & 3;
    int rb = wid * 16;

    for (int idx = tid; idx < 64 * 16; idx += 128) {
        int r = idx >> 4, c4 = (idx & 15) * 4;
        float4 a = *(const float4*)(Q + (size_t)(q0 + r) * DIMD + c4);
        a.x *= 0.125f; a.y *= 0.125f; a.z *= 0.125f; a.w *= 0.125f;
        *(float4*)&Ps[r * FLDS + c4] = a;
    }
    __syncthreads();
    uint32_t qf[8][4];
    #pragma unroll
    for (int ki = 0; ki < 8; ki++) {
        int ks = ki * 8;
        qf[ki][0] = __float_as_uint(Ps[(rb + gid    ) * FLDS + ks + tg    ]);
        qf[ki][1] = __float_as_uint(Ps[(rb + gid + 8) * FLDS + ks + tg    ]);
        qf[ki][2] = __float_as_uint(Ps[(rb + gid    ) * FLDS + ks + tg + 4]);
        qf[ki][3] = __float_as_uint(Ps[(rb + gid + 8) * FLDS + ks + tg + 4]);
    }
    __syncthreads();

    float m0 = -1e30f, m1 = -1e30f, l0 = 0.0f, l1 = 0.0f;
    float o[8][4] = {};

    for (int t0 = 0; t0 < SEQ; t0 += 64) {
        for (int idx = tid; idx < 64 * 16; idx += 128) {
            int r = idx >> 4, c4 = (idx & 15) * 4;
            *(float4*)&Ks[r * FLDS + c4] =
                *(const float4*)(K + (size_t)(t0 + r) * DIMD + c4);
            *(float4*)&Vs[r * FLDS + c4] =
                *(const float4*)(V + (size_t)(t0 + r) * DIMD + c4);
        }
        __syncthreads();

        float s[8][4] = {};
        #pragma unroll
        for (int ki = 0; ki < 8; ki++) {
            int ks = ki * 8;
            #pragma unroll
            for (int nt = 0; nt < 8; nt++) {
                uint32_t bf[2];
                bf[0] = __float_as_uint(Ks[(nt * 8 + gid) * FLDS + ks + tg    ]);
                bf[1] = __float_as_uint(Ks[(nt * 8 + gid) * FLDS + ks + tg + 4]);
                mma_tf32(s[nt], qf[ki], bf);
            }
        }

        float tm0 = -1e30f, tm1 = -1e30f;
        #pragma unroll
        for (int nt = 0; nt < 8; nt++) {
            tm0 = fmaxf(tm0, fmaxf(s[nt][0], s[nt][1]));
            tm1 = fmaxf(tm1, fmaxf(s[nt][2], s[nt][3]));
        }
        tm0 = fmaxf(tm0, __shfl_xor_sync(0xffffffffu, tm0, 1));
        tm0 = fmaxf(tm0, __shfl_xor_sync(0xffffffffu, tm0, 2));
        tm1 = fmaxf(tm1, __shfl_xor_sync(0xffffffffu, tm1, 1));
        tm1 = fmaxf(tm1, __shfl_xor_sync(0xffffffffu, tm1, 2));
        float nm0 = fmaxf(m0, tm0), nm1 = fmaxf(m1, tm1);
        float r0 = __expf(m0 - nm0), r1 = __expf(m1 - nm1);
        float sum0 = 0.0f, sum1 = 0.0f;
        #pragma unroll
        for (int nt = 0; nt < 8; nt++) {
            s[nt][0] = __expf(s[nt][0] - nm0);
            s[nt][1] = __expf(s[nt][1] - nm0);
            s[nt][2] = __expf(s[nt][2] - nm1);
            s[nt][3] = __expf(s[nt][3] - nm1);
            sum0 += s[nt][0] + s[nt][1];
            sum1 += s[nt][2] + s[nt][3];
        }
        sum0 += __shfl_xor_sync(0xffffffffu, sum0, 1);
        sum0 += __shfl_xor_sync(0xffffffffu, sum0, 2);
        sum1 += __shfl_xor_sync(0xffffffffu, sum1, 1);
        sum1 += __shfl_xor_sync(0xffffffffu, sum1, 2);
        l0 = l0 * r0 + sum0;
        l1 = l1 * r1 + sum1;
        m0 = nm0; m1 = nm1;
        #pragma unroll
        for (int nt = 0; nt < 8; nt++) {
            o[nt][0] *= r0; o[nt][1] *= r0;
            o[nt][2] *= r1; o[nt][3] *= r1;
        }

        #pragma unroll
        for (int nt = 0; nt < 8; nt++) {
            *(float2*)&Ps[(rb + gid    ) * FLDS + nt * 8 + tg * 2] =
                make_float2(s[nt][0], s[nt][1]);
            *(float2*)&Ps[(rb + gid + 8) * FLDS + nt * 8 + tg * 2] =
                make_float2(s[nt][2], s[nt][3]);
        }
        __syncthreads();

        #pragma unroll
        for (int ki = 0; ki < 8; ki++) {
            int ks = ki * 8;
            uint32_t af[4];
            af[0] = __float_as_uint(Ps[(rb + gid    ) * FLDS + ks + tg    ]);
            af[1] = __float_as_uint(Ps[(rb + gid + 8) * FLDS + ks + tg    ]);
            af[2] = __float_as_uint(Ps[(rb + gid    ) * FLDS + ks + tg + 4]);
            af[3] = __float_as_uint(Ps[(rb + gid + 8) * FLDS + ks + tg + 4]);
            #pragma unroll
            for (int nt = 0; nt < 8; nt++) {
                uint32_t bf[2];
                bf[0] = __float_as_uint(Vs[(ks + tg    ) * FLDS + nt * 8 + gid]);
                bf[1] = __float_as_uint(Vs[(ks + tg + 4) * FLDS + nt * 8 + gid]);
                mma_tf32(o[nt], af, bf);
            }
        }
        __syncthreads();
    }

    float inv0 = 1.0f / l0, inv1 = 1.0f / l1;
    int row0 = q0 + rb + gid, row1 = row0 + 8;
    #pragma unroll
    for (int nt = 0; nt < 8; nt++) {
        int col = nt * 8 + tg * 2;
        *(float2*)(O + (size_t)row0 * DIMD + col) =
            make_float2(o[nt][0] * inv0, o[nt][1] * inv0);
        *(float2*)(O + (size_t)row1 * DIMD + col) =
            make_float2(o[nt][2] * inv1, o[nt][3] * inv1);
    }
}

// ---------------- launch ----------------------------------------------------
extern "C" void kernel_launch(void* const* d_in, const int* in_sizes, int n_in,
                              void* d_out, int out_size) {
    const float* x   = (const float*)d_in[0];
    const float* Wq  = (const float*)d_in[1];
    const float* Wk  = (const float*)d_in[2];
    const float* Wv  = (const float*)d_in[3];
    const float* Wo  = (const float*)d_in[4];
    const float* bo  = (const float*)d_in[5];
    const float* W1  = (const float*)d_in[6];
    const float* b1  = (const float*)d_in[7];
    const float* W2  = (const float*)d_in[8];
    const float* b2  = (const float*)d_in[9];
    const float* g1  = (const float*)d_in[10];
    const float* be1 = (const float*)d_in[11];
    const float* g2  = (const float*)d_in[12];
    const float* be2 = (const float*)d_in[13];
    float* out = (float*)d_out;

    float *h, *q, *k, *v, *att, *xm;
    __nv_bfloat16 *h2h, *h2l, *ffh, *ffl, *w1h, *w1l, *w2h, *w2l;
    cudaGetSymbolAddress((void**)&h,   g_h);
    cudaGetSymbolAddress((void**)&q,   g_q);
    cudaGetSymbolAddress((void**)&k,   g_k);
    cudaGetSymbolAddress((void**)&v,   g_v);
    cudaGetSymbolAddress((void**)&att, g_att);
    cudaGetSymbolAddress((void**)&xm,  g_xm);
    cudaGetSymbolAddress((void**)&h2h, g_h2h);
    cudaGetSymbolAddress((void**)&h2l, g_h2l);
    cudaGetSymbolAddress((void**)&ffh, g_ffh);
    cudaGetSymbolAddress((void**)&ffl, g_ffl);
    cudaGetSymbolAddress((void**)&w1h, g_w1h); cudaGetSymbolAddress((void**)&w1l, g_w1l);
    cudaGetSymbolAddress((void**)&w2h, g_w2h); cudaGetSymbolAddress((void**)&w2l, g_w2l);

    cudaFuncSetAttribute(flash_tf32,
                         cudaFuncAttributeMaxDynamicSharedMemorySize, FSM_BYTES);
    cudaFuncSetAttribute(gemm_tf32<0>,
                         cudaFuncAttributeMaxDynamicSharedMemorySize, TF_SMEM);
    cudaFuncSetAttribute(gemm_tf32<3>,
                         cudaFuncAttributeMaxDynamicSharedMemorySize, TF_SMEM);
    cudaFuncSetAttribute(gemm_bf16p<2, 1>,
                         cudaFuncAttributeMaxDynamicSharedMemorySize, BF_SMEM);
    cudaFuncSetAttribute(gemm_bf16p<3, 0>,
                         cudaFuncAttributeMaxDynamicSharedMemorySize, BF_SMEM);

    dim3 gProj(DIMD / 128, BN_TOK / 128);       // (4, 64)
    dim3 gMlp(MLPD / 128, BN_TOK / 128);        // (16, 64)
    dim3 wg2(MLPD / 32, DIMD / 32), wg3(DIMD / 32, MLPD / 32);
    dim3 wthr(32, 8);

    // 0) weight transpose + bf16 split for MLP weights
    wsplit_kernel<<<wg2, wthr>>>(W1, w1h, w1l, DIMD, MLPD);
    wsplit_kernel<<<wg3, wthr>>>(W2, w2h, w2l, MLPD, DIMD);
    // 1) h = LN(x; g1, be1)
    ln_kernel<<<BN_TOK, 128>>>(x, g1, be1, h);
    // 2) q, k, v projections (single-pass tf32, cp.async pipelined)
    gemm_tf32<0><<<gProj, 256, TF_SMEM>>>(h, Wq, nullptr, nullptr, q, BN_TOK, DIMD, DIMD);
    gemm_tf32<0><<<gProj, 256, TF_SMEM>>>(h, Wk, nullptr, nullptr, k, BN_TOK, DIMD, DIMD);
    gemm_tf32<0><<<gProj, 256, TF_SMEM>>>(h, Wv, nullptr, nullptr, v, BN_TOK, DIMD, DIMD);
    // 3-5) fused flash attention
    flash_tf32<<<dim3(SEQ / 64, BATCH * HEADS), 128, FSM_BYTES>>>(q, k, v, att);
    // 6) xm = x + att @ Wo + bo
    gemm_tf32<3><<<gProj, 256, TF_SMEM>>>(att, Wo, bo, x, xm, BN_TOK, DIMD, DIMD);
    // 7) h2 = LN(xm; g2, be2) -> pre-split bf16
    ln_bf16_kernel<<<BN_TOK, 128>>>(xm, g2, be2, h2h, h2l);
    // 8) ff = gelu(h2 @ W1 + b1) -> pre-split bf16 (bf16x3, cp.async pipelined)
    gemm_bf16p<2, 1><<<gMlp, 256, BF_SMEM>>>(h2h, h2l, w1h, w1l, b1, nullptr,
                                             nullptr, ffh, ffl, BN_TOK, MLPD, DIMD);
    // 9) out = xm + ff @ W2 + b2
    gemm_bf16p<3, 0><<<gProj, 256, BF_SMEM>>>(ffh, ffl, w2h, w2l, b2, xm,
                                              out, nullptr, nullptr, BN_TOK, DIMD, MLPD);
}